// round 16
// baseline (speedup 1.0000x reference)
#include <cuda_runtime.h>
#include <cuda_fp16.h>
#include <cstdint>
#include <cstddef>

#define K_DIM 4096
#define N_DIM 11008
#define M_DIM 4096
#define QROWS (K_DIM / 8)

#define BM 128
#define BN 128
#define BK 64
#define A_ST (BK + 8)            // 72 halves = 144B stride (conflict-free ldmatrix)
#define B_ST (BN + 8)            // 136 halves = 272B stride
#define NSTAGE 3
#define A_TILE_H (BM * A_ST)     // 9216 halves
#define B_TILE_H (BK * B_ST)     // 8704 halves
#define STAGE_H (A_TILE_H + B_TILE_H)      // 17920 halves = 35840 B
#define SMEM_BYTES (NSTAGE * STAGE_H * 2)  // 107520 B

// Device-code-only globals (host symbol address = ATS host shadow = zeros!).
__device__ __half g_W[(size_t)K_DIM * N_DIM];    // dequantized W [K, N]
__device__ __half g_X[(size_t)M_DIM * K_DIM];    // x as fp16 [M, K]

// ---------------------------------------------------------------------------
// Prep (fused): blocks [0,NCVT) convert x fp32->fp16, rest dequant int4 -> g_W.
// ---------------------------------------------------------------------------
#define NCVT (M_DIM * K_DIM / 1024)              // 16384
#define DQ_CBLK (N_DIM / 256)                    // 43
#define NDQ (DQ_CBLK * QROWS)                    // 22016

__global__ void prep_kernel(const float* __restrict__ x,
                            const int* __restrict__ qw,
                            const int* __restrict__ qz,
                            const float* __restrict__ sc) {
    int b = blockIdx.x;
    if (b < NCVT) {
        size_t i = ((size_t)b * 256 + threadIdx.x) * 4;
        float4 v = *reinterpret_cast<const float4*>(x + i);
        *reinterpret_cast<__half2*>(&g_X[i]) = __floats2half2_rn(v.x, v.y);
        *reinterpret_cast<__half2*>(&g_X[i + 2]) = __floats2half2_rn(v.z, v.w);
        return;
    }
    b -= NCVT;
    int c = (b % DQ_CBLK) * 256 + threadIdx.x;
    int kk = b / DQ_CBLK;
    if (c >= N_DIM) return;
    int packed = qw[kk * N_DIM + c];
    int g = kk >> 4;
    int z = (qz[g * (N_DIM / 8) + (c >> 3)] >> ((c & 7) * 4)) & 15;
    float s = sc[g * N_DIM + c];
    size_t base = (size_t)kk * 8 * N_DIM + c;
#pragma unroll
    for (int i = 0; i < 8; i++) {
        int q = (packed >> (i * 4)) & 15;
        g_W[base + (size_t)i * N_DIM] = __float2half((float)(q - z) * s);
    }
}

// ---------------------------------------------------------------------------
// GEMM: 128x128x64 tile, 8 warps (2x4), 3-stage cp.async, cross-stage
// fragment prefetch (buf0 of stage kt+1 loaded before the kt+1 barrier).
// ---------------------------------------------------------------------------
__device__ __forceinline__ void cp16(uint32_t s, const void* g) {
    asm volatile("cp.async.cg.shared.global [%0], [%1], 16;\n" ::"r"(s), "l"(g) : "memory");
}

__device__ __forceinline__ void issue_tile(int tid, uint32_t sa, uint32_t sb,
                                           const __half* Ag, const __half* Bg,
                                           int k0) {
#pragma unroll
    for (int t = 0; t < 4; t++) {               // A: 128 rows x 8 chunks = 1024
        int ci = tid + t * 256;
        int ar = ci >> 3, ac = (ci & 7) << 3;
        cp16(sa + (ar * A_ST + ac) * 2, Ag + (size_t)ar * K_DIM + k0 + ac);
    }
#pragma unroll
    for (int t = 0; t < 4; t++) {               // B: 64 rows x 16 chunks = 1024
        int ci = tid + t * 256;
        int br = ci >> 4, bc = (ci & 15) << 3;
        cp16(sb + (br * B_ST + bc) * 2, Bg + (size_t)(k0 + br) * N_DIM + bc);
    }
    asm volatile("cp.async.commit_group;\n" ::: "memory");
}

__device__ __forceinline__ void load_frags(uint32_t sa, uint32_t sb, int wm, int wn,
                                           int lane, int ks, uint32_t af[4][4],
                                           uint32_t bf[2][4]) {
#pragma unroll
    for (int mi = 0; mi < 4; mi++) {
        int m = wm * 64 + mi * 16 + (lane & 15);
        int kc = ks * 16 + ((lane >> 4) << 3);
        uint32_t addr = sa + (m * A_ST + kc) * 2;
        asm volatile("ldmatrix.sync.aligned.m8n8.x4.shared.b16 {%0,%1,%2,%3}, [%4];\n"
                     : "=r"(af[mi][0]), "=r"(af[mi][1]), "=r"(af[mi][2]), "=r"(af[mi][3])
                     : "r"(addr));
    }
#pragma unroll
    for (int nj = 0; nj < 2; nj++) {
        int kr = ks * 16 + (lane & 15);
        int n = wn * 32 + nj * 16 + ((lane >> 4) << 3);
        uint32_t addr = sb + (kr * B_ST + n) * 2;
        asm volatile("ldmatrix.sync.aligned.m8n8.x4.trans.shared.b16 {%0,%1,%2,%3}, [%4];\n"
                     : "=r"(bf[nj][0]), "=r"(bf[nj][1]), "=r"(bf[nj][2]), "=r"(bf[nj][3])
                     : "r"(addr));
    }
}

__device__ __forceinline__ void do_mmas(const uint32_t af[4][4], const uint32_t bf[2][4],
                                        float acc[4][4][4]) {
#pragma unroll
    for (int mi = 0; mi < 4; mi++)
#pragma unroll
        for (int ni = 0; ni < 4; ni++) {
            uint32_t b0 = bf[ni >> 1][(ni & 1) * 2];
            uint32_t b1 = bf[ni >> 1][(ni & 1) * 2 + 1];
            asm volatile(
                "mma.sync.aligned.m16n8k16.row.col.f32.f16.f16.f32 "
                "{%0,%1,%2,%3}, {%4,%5,%6,%7}, {%8,%9}, {%0,%1,%2,%3};\n"
                : "+f"(acc[mi][ni][0]), "+f"(acc[mi][ni][1]), "+f"(acc[mi][ni][2]),
                  "+f"(acc[mi][ni][3])
                : "r"(af[mi][0]), "r"(af[mi][1]), "r"(af[mi][2]), "r"(af[mi][3]),
                  "r"(b0), "r"(b1));
        }
}

__global__ void __launch_bounds__(256, 2)
gemm_kernel(const float* __restrict__ bias, float* __restrict__ C) {
    extern __shared__ __align__(16) __half smem[];

    const int tid = threadIdx.x;
    const int lane = tid & 31;
    const int warp = tid >> 5;
    const int wm = warp >> 2;   // 0..1
    const int wn = warp & 3;    // 0..3
    const int bm = blockIdx.x;  // bm-major: wave = all bm x few bn (B reused in L2)
    const int bn = blockIdx.y;

    const __half* Ag = g_X + (size_t)bm * BM * K_DIM;
    const __half* Bg = g_W + (size_t)bn * BN;

    uint32_t sA[NSTAGE], sB[NSTAGE];
#pragma unroll
    for (int s = 0; s < NSTAGE; s++) {
        sA[s] = (uint32_t)__cvta_generic_to_shared(smem + s * STAGE_H);
        sB[s] = sA[s] + A_TILE_H * 2;
    }

    float acc[4][4][4];
#pragma unroll
    for (int i = 0; i < 4; i++)
#pragma unroll
        for (int j = 0; j < 4; j++)
#pragma unroll
            for (int k = 0; k < 4; k++) acc[i][j][k] = 0.0f;

    const int NKI = K_DIM / BK;  // 64
    issue_tile(tid, sA[0], sB[0], Ag, Bg, 0);
    issue_tile(tid, sA[1], sB[1], Ag, Bg, BK);

    uint32_t af[2][4][4], bf[2][2][4];

    // Prologue: stage 0 resident -> preload its ks=0 fragments.
    asm volatile("cp.async.wait_group 1;\n" ::: "memory");
    __syncthreads();
    load_frags(sA[0], sB[0], wm, wn, lane, 0, af[0], bf[0]);

    for (int kt = 0; kt < NKI; kt++) {
        int cur = kt % NSTAGE;
        // Writes stage (kt+2)%3; readers of that stage (iteration kt-1) were
        // ordered by the end-of-(kt-1) barrier.
        if (kt + 2 < NKI)
            issue_tile(tid, sA[(kt + 2) % NSTAGE], sB[(kt + 2) % NSTAGE], Ag, Bg,
                       (kt + 2) * BK);

#pragma unroll
        for (int ks = 0; ks < 4; ks++) {
            if (ks < 3)
                load_frags(sA[cur], sB[cur], wm, wn, lane, ks + 1, af[(ks + 1) & 1],
                           bf[(ks + 1) & 1]);
            do_mmas(af[ks & 1], bf[ks & 1], acc);
        }

        if (kt + 1 < NKI) {
            // Issued groups: g0..g(kt+2); <=1 pending => g(kt+1) resident.
            asm volatile("cp.async.wait_group 1;\n" ::: "memory");
            __syncthreads();   // also orders this kt's smem reads before the
                               // overwrite of stage kt%3 at top of kt+1
            // Cross-stage prefetch: barrier wait overlapped the MMA drain,
            // and kt+1 starts on ready registers.
            int nxt = (kt + 1) % NSTAGE;
            load_frags(sA[nxt], sB[nxt], wm, wn, lane, 0, af[0], bf[0]);
        }
    }

    // Epilogue: fp16(acc) + fp16(bias) in fp16 (reference semantics), widen to fp32.
#pragma unroll
    for (int mi = 0; mi < 4; mi++) {
        int r = bm * BM + wm * 64 + mi * 16 + (lane >> 2);
#pragma unroll
        for (int ni = 0; ni < 4; ni++) {
            int col = bn * BN + wn * 32 + ni * 8 + (lane & 3) * 2;
            __half b0 = __float2half_rn(bias[col]);
            __half b1 = __float2half_rn(bias[col + 1]);
            float2 v0, v1;
            v0.x = __half2float(__hadd(__float2half_rn(acc[mi][ni][0]), b0));
            v0.y = __half2float(__hadd(__float2half_rn(acc[mi][ni][1]), b1));
            v1.x = __half2float(__hadd(__float2half_rn(acc[mi][ni][2]), b0));
            v1.y = __half2float(__hadd(__float2half_rn(acc[mi][ni][3]), b1));
            *reinterpret_cast<float2*>(C + (size_t)r * N_DIM + col) = v0;
            *reinterpret_cast<float2*>(C + (size_t)(r + 8) * N_DIM + col) = v1;
        }
    }
}

extern "C" void kernel_launch(void* const* d_in, const int* in_sizes, int n_in,
                              void* d_out, int out_size) {
    const float* x = nullptr;
    const int* qw = nullptr;
    const int* qz = nullptr;
    const float* sc = nullptr;
    const float* bias = nullptr;
    for (int i = 0; i < n_in; i++) {
        int sz = in_sizes[i];
        if (sz == QROWS * N_DIM) qw = (const int*)d_in[i];
        else if (sz == 32 * (N_DIM / 8)) qz = (const int*)d_in[i];
        else if (sz == 32 * N_DIM) sc = (const float*)d_in[i];
        else if (sz == N_DIM) bias = (const float*)d_in[i];
        else if (sz == M_DIM * K_DIM) x = (const float*)d_in[i];
    }
    float* out = (float*)d_out;

    prep_kernel<<<NCVT + NDQ, 256>>>(x, qw, qz, sc);

    cudaFuncSetAttribute(gemm_kernel, cudaFuncAttributeMaxDynamicSharedMemorySize,
                         SMEM_BYTES);
    dim3 g_grid(M_DIM / BM, N_DIM / BN);  // (32, 86) — bm-major
    gemm_kernel<<<g_grid, 256, SMEM_BYTES>>>(bias, out);
}

// round 17
// speedup vs baseline: 1.1523x; 1.1523x over previous
#include <cuda_runtime.h>
#include <cuda_fp16.h>
#include <cstdint>
#include <cstddef>

#define K_DIM 4096
#define N_DIM 11008
#define M_DIM 4096
#define QROWS (K_DIM / 8)

#define BM 128
#define BN 128
#define BK 64
#define A_ST (BK + 8)            // 72 halves = 144B stride (conflict-free ldmatrix)
#define B_ST (BN + 8)            // 136 halves = 272B stride
#define NSTAGE 3
#define A_TILE_H (BM * A_ST)     // 9216 halves
#define B_TILE_H (BK * B_ST)     // 8704 halves
#define STAGE_H (A_TILE_H + B_TILE_H)        // 17920 halves
#define STAGE_BYTES (STAGE_H * 2)            // 35840 B
#define MBAR_BYTES 64
#define SMEM_BYTES (MBAR_BYTES + NSTAGE * STAGE_BYTES)   // 107584 B

// Device-code-only globals (host symbol address = ATS host shadow = zeros!).
__device__ __half g_W[(size_t)K_DIM * N_DIM];    // dequantized W [K, N]
__device__ __half g_X[(size_t)M_DIM * K_DIM];    // x as fp16 [M, K]

// ---------------------------------------------------------------------------
// Prep (fused): blocks [0,NCVT) convert x fp32->fp16, rest dequant int4 -> g_W.
// ---------------------------------------------------------------------------
#define NCVT (M_DIM * K_DIM / 1024)              // 16384
#define DQ_CBLK (N_DIM / 256)                    // 43
#define NDQ (DQ_CBLK * QROWS)                    // 22016

__global__ void prep_kernel(const float* __restrict__ x,
                            const int* __restrict__ qw,
                            const int* __restrict__ qz,
                            const float* __restrict__ sc) {
    int b = blockIdx.x;
    if (b < NCVT) {
        size_t i = ((size_t)b * 256 + threadIdx.x) * 4;
        float4 v = *reinterpret_cast<const float4*>(x + i);
        *reinterpret_cast<__half2*>(&g_X[i]) = __floats2half2_rn(v.x, v.y);
        *reinterpret_cast<__half2*>(&g_X[i + 2]) = __floats2half2_rn(v.z, v.w);
        return;
    }
    b -= NCVT;
    int c = (b % DQ_CBLK) * 256 + threadIdx.x;
    int kk = b / DQ_CBLK;
    if (c >= N_DIM) return;
    int packed = qw[kk * N_DIM + c];
    int g = kk >> 4;
    int z = (qz[g * (N_DIM / 8) + (c >> 3)] >> ((c & 7) * 4)) & 15;
    float s = sc[g * N_DIM + c];
    size_t base = (size_t)kk * 8 * N_DIM + c;
#pragma unroll
    for (int i = 0; i < 8; i++) {
        int q = (packed >> (i * 4)) & 15;
        g_W[base + (size_t)i * N_DIM] = __float2half((float)(q - z) * s);
    }
}

// ---------------------------------------------------------------------------
// mbarrier helpers (baseline sm_90 PTX — valid under compute_103)
// ---------------------------------------------------------------------------
__device__ __forceinline__ void mbar_init(uint32_t a, uint32_t cnt) {
    asm volatile("mbarrier.init.shared.b64 [%0], %1;" ::"r"(a), "r"(cnt) : "memory");
}
__device__ __forceinline__ void mbar_arrive(uint32_t a) {
    asm volatile("{\n\t.reg .b64 t;\n\tmbarrier.arrive.shared.b64 t, [%0];\n\t}"
                 ::"r"(a) : "memory");
}
__device__ __forceinline__ void cp_arrive(uint32_t a) {
    asm volatile("cp.async.mbarrier.arrive.noinc.shared.b64 [%0];" ::"r"(a) : "memory");
}
__device__ __forceinline__ void mbar_wait(uint32_t a, uint32_t ph) {
    asm volatile(
        "{\n\t.reg .pred P;\n\t"
        "W_%=:\n\t"
        "mbarrier.try_wait.parity.shared.b64 P, [%0], %1;\n\t"
        "@!P bra W_%=;\n\t}"
        ::"r"(a), "r"(ph) : "memory");
}

// ---------------------------------------------------------------------------
// GEMM: 128x128x64 tile, 8 warps (2x4), 3-stage cp.async pipeline with
// mbarrier full/empty sync (no CTA-wide __syncthreads in the mainloop —
// warps decouple; the barrier convoy is gone).
// ---------------------------------------------------------------------------
__device__ __forceinline__ void cp16(uint32_t s, const void* g) {
    asm volatile("cp.async.cg.shared.global [%0], [%1], 16;\n" ::"r"(s), "l"(g) : "memory");
}

__device__ __forceinline__ void issue_tile(int tid, uint32_t sa, uint32_t sb,
                                           const __half* Ag, const __half* Bg,
                                           int k0) {
#pragma unroll
    for (int t = 0; t < 4; t++) {               // A: 128 rows x 8 chunks = 1024
        int ci = tid + t * 256;
        int ar = ci >> 3, ac = (ci & 7) << 3;
        cp16(sa + (ar * A_ST + ac) * 2, Ag + (size_t)ar * K_DIM + k0 + ac);
    }
#pragma unroll
    for (int t = 0; t < 4; t++) {               // B: 64 rows x 16 chunks = 1024
        int ci = tid + t * 256;
        int br = ci >> 4, bc = (ci & 15) << 3;
        cp16(sb + (br * B_ST + bc) * 2, Bg + (size_t)(k0 + br) * N_DIM + bc);
    }
}

__device__ __forceinline__ void load_frags(uint32_t sa, uint32_t sb, int wm, int wn,
                                           int lane, int ks, uint32_t af[4][4],
                                           uint32_t bf[2][4]) {
#pragma unroll
    for (int mi = 0; mi < 4; mi++) {
        int m = wm * 64 + mi * 16 + (lane & 15);
        int kc = ks * 16 + ((lane >> 4) << 3);
        uint32_t addr = sa + (m * A_ST + kc) * 2;
        asm volatile("ldmatrix.sync.aligned.m8n8.x4.shared.b16 {%0,%1,%2,%3}, [%4];\n"
                     : "=r"(af[mi][0]), "=r"(af[mi][1]), "=r"(af[mi][2]), "=r"(af[mi][3])
                     : "r"(addr));
    }
#pragma unroll
    for (int nj = 0; nj < 2; nj++) {
        int kr = ks * 16 + (lane & 15);
        int n = wn * 32 + nj * 16 + ((lane >> 4) << 3);
        uint32_t addr = sb + (kr * B_ST + n) * 2;
        asm volatile("ldmatrix.sync.aligned.m8n8.x4.trans.shared.b16 {%0,%1,%2,%3}, [%4];\n"
                     : "=r"(bf[nj][0]), "=r"(bf[nj][1]), "=r"(bf[nj][2]), "=r"(bf[nj][3])
                     : "r"(addr));
    }
}

__device__ __forceinline__ void do_mmas(const uint32_t af[4][4], const uint32_t bf[2][4],
                                        float acc[4][4][4]) {
#pragma unroll
    for (int mi = 0; mi < 4; mi++)
#pragma unroll
        for (int ni = 0; ni < 4; ni++) {
            uint32_t b0 = bf[ni >> 1][(ni & 1) * 2];
            uint32_t b1 = bf[ni >> 1][(ni & 1) * 2 + 1];
            asm volatile(
                "mma.sync.aligned.m16n8k16.row.col.f32.f16.f16.f32 "
                "{%0,%1,%2,%3}, {%4,%5,%6,%7}, {%8,%9}, {%0,%1,%2,%3};\n"
                : "+f"(acc[mi][ni][0]), "+f"(acc[mi][ni][1]), "+f"(acc[mi][ni][2]),
                  "+f"(acc[mi][ni][3])
                : "r"(af[mi][0]), "r"(af[mi][1]), "r"(af[mi][2]), "r"(af[mi][3]),
                  "r"(b0), "r"(b1));
        }
}

__global__ void __launch_bounds__(256, 2)
gemm_kernel(const float* __restrict__ bias, float* __restrict__ C) {
    extern __shared__ __align__(16) char smem[];
    const uint32_t sbase = (uint32_t)__cvta_generic_to_shared(smem);

    const int tid = threadIdx.x;
    const int lane = tid & 31;
    const int warp = tid >> 5;
    const int wm = warp >> 2;   // 0..1
    const int wn = warp & 3;    // 0..3
    const int bm = blockIdx.x;  // bm-major: wave = all bm x few bn (B reused in L2)
    const int bn = blockIdx.y;

    const __half* Ag = g_X + (size_t)bm * BM * K_DIM;
    const __half* Bg = g_W + (size_t)bn * BN;

    // Barriers: full[s] at sbase + 8s, empty[s] at sbase + 24 + 8s.
    if (tid == 0) {
#pragma unroll
        for (int s = 0; s < NSTAGE; s++) {
            mbar_init(sbase + 8 * s, 256);        // full: 256 cp-arrives
            mbar_init(sbase + 24 + 8 * s, 256);   // empty: 256 thread arrives
        }
    }
    __syncthreads();

    uint32_t sA[NSTAGE], sB[NSTAGE];
#pragma unroll
    for (int s = 0; s < NSTAGE; s++) {
        sA[s] = sbase + MBAR_BYTES + s * STAGE_BYTES;
        sB[s] = sA[s] + A_TILE_H * 2;
    }

    float acc[4][4][4];
#pragma unroll
    for (int i = 0; i < 4; i++)
#pragma unroll
        for (int j = 0; j < 4; j++)
#pragma unroll
            for (int k = 0; k < 4; k++) acc[i][j][k] = 0.0f;

    const int NKI = K_DIM / BK;  // 64
    issue_tile(tid, sA[0], sB[0], Ag, Bg, 0);
    cp_arrive(sbase + 0);
    issue_tile(tid, sA[1], sB[1], Ag, Bg, BK);
    cp_arrive(sbase + 8);

    uint32_t af[2][4][4], bf[2][2][4];

    for (int kt = 0; kt < NKI; kt++) {
        int s = kt % NSTAGE;
        mbar_wait(sbase + 8 * s, (uint32_t)(kt / 3) & 1u);   // data ready (acquire)
        load_frags(sA[s], sB[s], wm, wn, lane, 0, af[0], bf[0]);

        if (kt + 2 < NKI) {
            int ps = (kt + 2) % NSTAGE;
            int j = (kt + 2) / 3;                            // fill ordinal of stage ps
            if (j >= 1)
                mbar_wait(sbase + 24 + 8 * ps, (uint32_t)(j - 1) & 1u);  // stage free
            issue_tile(tid, sA[ps], sB[ps], Ag, Bg, (kt + 2) * BK);
            cp_arrive(sbase + 8 * ps);
        }

#pragma unroll
        for (int ks = 0; ks < 4; ks++) {
            if (ks < 3) {
                load_frags(sA[s], sB[s], wm, wn, lane, ks + 1, af[(ks + 1) & 1],
                           bf[(ks + 1) & 1]);
                if (ks == 2) mbar_arrive(sbase + 24 + 8 * s);  // last read of stage s done
            }
            do_mmas(af[ks & 1], bf[ks & 1], acc);
        }
    }

    // Epilogue: fp16(acc) + fp16(bias) in fp16 (reference semantics), widen to fp32.
#pragma unroll
    for (int mi = 0; mi < 4; mi++) {
        int r = bm * BM + wm * 64 + mi * 16 + (lane >> 2);
#pragma unroll
        for (int ni = 0; ni < 4; ni++) {
            int col = bn * BN + wn * 32 + ni * 8 + (lane & 3) * 2;
            __half b0 = __float2half_rn(bias[col]);
            __half b1 = __float2half_rn(bias[col + 1]);
            float2 v0, v1;
            v0.x = __half2float(__hadd(__float2half_rn(acc[mi][ni][0]), b0));
            v0.y = __half2float(__hadd(__float2half_rn(acc[mi][ni][1]), b1));
            v1.x = __half2float(__hadd(__float2half_rn(acc[mi][ni][2]), b0));
            v1.y = __half2float(__hadd(__float2half_rn(acc[mi][ni][3]), b1));
            *reinterpret_cast<float2*>(C + (size_t)r * N_DIM + col) = v0;
            *reinterpret_cast<float2*>(C + (size_t)(r + 8) * N_DIM + col) = v1;
        }
    }
}

extern "C" void kernel_launch(void* const* d_in, const int* in_sizes, int n_in,
                              void* d_out, int out_size) {
    const float* x = nullptr;
    const int* qw = nullptr;
    const int* qz = nullptr;
    const float* sc = nullptr;
    const float* bias = nullptr;
    for (int i = 0; i < n_in; i++) {
        int sz = in_sizes[i];
        if (sz == QROWS * N_DIM) qw = (const int*)d_in[i];
        else if (sz == 32 * (N_DIM / 8)) qz = (const int*)d_in[i];
        else if (sz == 32 * N_DIM) sc = (const float*)d_in[i];
        else if (sz == N_DIM) bias = (const float*)d_in[i];
        else if (sz == M_DIM * K_DIM) x = (const float*)d_in[i];
    }
    float* out = (float*)d_out;

    prep_kernel<<<NCVT + NDQ, 256>>>(x, qw, qz, sc);

    cudaFuncSetAttribute(gemm_kernel, cudaFuncAttributeMaxDynamicSharedMemorySize,
                         SMEM_BYTES);
    dim3 g_grid(M_DIM / BM, N_DIM / BN);  // (32, 86) — bm-major
    gemm_kernel<<<g_grid, 256, SMEM_BYTES>>>(bias, out);
}